// round 16
// baseline (speedup 1.0000x reference)
#include <cuda_runtime.h>
#include <cuda_fp16.h>
#include <math.h>
#include <stdint.h>

#define S_LEN  4096
#define DM     512
#define NHEADS 8
#define DKH    64
#define BSDM   (8192UL * 512UL)

__device__ float g_scratch[4UL * 8192 * 512];   // 64 MB = 32M halves

// ---------------------------------------------------------------------------
// mma / ldmatrix / cp.async helpers
// ---------------------------------------------------------------------------
__device__ __forceinline__ void mma_f16(float* c, const uint32_t* a, const uint32_t* b) {
    asm volatile("mma.sync.aligned.m16n8k16.row.col.f32.f16.f16.f32 "
        "{%0,%1,%2,%3}, {%4,%5,%6,%7}, {%8,%9}, {%0,%1,%2,%3};"
        : "+f"(c[0]), "+f"(c[1]), "+f"(c[2]), "+f"(c[3])
        : "r"(a[0]), "r"(a[1]), "r"(a[2]), "r"(a[3]), "r"(b[0]), "r"(b[1]));
}
#define LDM_X4(r0, r1, r2, r3, addr) \
    asm volatile("ldmatrix.sync.aligned.m8n8.x4.shared.b16 {%0,%1,%2,%3}, [%4];" \
        : "=r"(r0), "=r"(r1), "=r"(r2), "=r"(r3) : "r"(addr))
#define LDM_X4T(r0, r1, r2, r3, addr) \
    asm volatile("ldmatrix.sync.aligned.m8n8.x4.trans.shared.b16 {%0,%1,%2,%3}, [%4];" \
        : "=r"(r0), "=r"(r1), "=r"(r2), "=r"(r3) : "r"(addr))
#define CP_ASYNC16(dst, src) \
    asm volatile("cp.async.cg.shared.global [%0], [%1], 16;" :: "r"(dst), "l"(src))
#define CP_COMMIT() asm volatile("cp.async.commit_group;" ::: "memory")
#define CP_WAIT0()  asm volatile("cp.async.wait_group 0;" ::: "memory")

__device__ __forceinline__ uint32_t smem_u32(const void* p) {
    uint32_t a;
    asm("{ .reg .u64 t; cvta.to.shared.u64 t, %1; cvt.u32.u64 %0, t; }" : "=r"(a) : "l"(p));
    return a;
}
__device__ __forceinline__ uint32_t packh2(float lo, float hi) {
    __half2 h = __floats2half2_rn(lo, hi);
    return *(uint32_t*)&h;
}
__device__ __forceinline__ uint2 packh4(float4 f) {
    return make_uint2(packh2(f.x, f.y), packh2(f.z, f.w));
}
__device__ __forceinline__ uint32_t ex2h2(uint32_t x) {
    uint32_t r; asm("ex2.approx.f16x2 %0, %1;" : "=r"(r) : "r"(x)); return r;
}

#define A_OFF(RB)  (((lane & 15) * (RB)) + ((lane >> 4) * 16))
#define B_OFF(RB)  (((((lane >> 4) & 1) * 8 + (lane & 7)) * (RB)) + (((lane >> 3) & 1) * 16))

// ---------------------------------------------------------------------------
// fp32 -> fp16 pre-pass
// ---------------------------------------------------------------------------
__global__ __launch_bounds__(256) void cvt_qkv(
    const float* __restrict__ q, const float* __restrict__ k, const float* __restrict__ v,
    __half* __restrict__ qh, __half* __restrict__ kh, __half* __restrict__ vh)
{
    const float* src; __half* dst;
    if (blockIdx.y == 0)      { src = q; dst = qh; }
    else if (blockIdx.y == 1) { src = k; dst = kh; }
    else                      { src = v; dst = vh; }
    size_t i = ((size_t)blockIdx.x * 256 + threadIdx.x) * 8;
    float4 f0 = *(const float4*)(src + i);
    float4 f1 = *(const float4*)(src + i + 4);
    *(uint4*)(dst + i) = make_uint4(packh2(f0.x, f0.y), packh2(f0.z, f0.w),
                                    packh2(f1.x, f1.y), packh2(f1.z, f1.w));
}

__global__ __launch_bounds__(256) void cvt_w(
    const float* __restrict__ Wq, const float* __restrict__ Wk,
    const float* __restrict__ Wv, const float* __restrict__ Wo,
    __half* __restrict__ Wh)
{
    const float* src;
    if (blockIdx.y == 0)      src = Wq;
    else if (blockIdx.y == 1) src = Wk;
    else if (blockIdx.y == 2) src = Wv;
    else                      src = Wo;
    __half* dst = Wh + (size_t)blockIdx.y * DM * DM;
    size_t i = ((size_t)blockIdx.x * 256 + threadIdx.x) * 8;
    float4 f0 = *(const float4*)(src + i);
    float4 f1 = *(const float4*)(src + i + 4);
    *(uint4*)(dst + i) = make_uint4(packh2(f0.x, f0.y), packh2(f0.z, f0.w),
                                    packh2(f1.x, f1.y), packh2(f1.z, f1.w));
}

// ---------------------------------------------------------------------------
// GEMM body (all-fp16 operands, fp32 accum), double-buffered. Unchanged (R13).
// ---------------------------------------------------------------------------
#define GST  40
#define GSTB 80
#define GASZ (128 * GST)
#define GWSZ (64 * GST)

template<typename Tout>
__device__ __forceinline__ void gemm_body(
    const __half* __restrict__ A, const __half* __restrict__ W,
    const float* __restrict__ bias, Tout* __restrict__ C,
    __half* As, __half* Ws)
{
    const int t = threadIdx.x;
    const int w = t >> 5, lane = t & 31;
    const int g = lane >> 2, tig = lane & 3;
    const int m0 = blockIdx.y * 128, n0 = blockIdx.x * 64;
    const int wm = (w >> 1) * 32, wn = (w & 1) * 32;
    const int ar = t >> 1, ac = (t & 1) * 16;
    const int wr = t >> 2, wc = (t & 3) * 8;

    uint32_t uA[2], uW[2];
    uA[0] = smem_u32(As) + wm * GSTB + A_OFF(GSTB);
    uA[1] = uA[0] + GASZ * 2;
    uW[0] = smem_u32(Ws) + wn * GSTB + B_OFF(GSTB);
    uW[1] = uW[0] + GWSZ * 2;

    {
        const __half* sa = A + (size_t)(m0 + ar) * DM + ac;
        *(uint4*)&As[ar * GST + ac]     = *(const uint4*)sa;
        *(uint4*)&As[ar * GST + ac + 8] = *(const uint4*)(sa + 8);
        *(uint4*)&Ws[wr * GST + wc]     = *(const uint4*)(W + (size_t)(n0 + wr) * DM + wc);
    }
    __syncthreads();

    float c[2][4][4] = {};

    for (int kt = 0; kt < DM / 32; kt++) {
        const int cur = kt & 1;
        const bool pf = (kt < DM / 32 - 1);

        uint4 pah[2], pwh;
        if (pf) {
            const int k0 = (kt + 1) * 32;
            const __half* sa = A + (size_t)(m0 + ar) * DM + k0 + ac;
            pah[0] = *(const uint4*)sa; pah[1] = *(const uint4*)(sa + 8);
            pwh = *(const uint4*)(W + (size_t)(n0 + wr) * DM + k0 + wc);
        }

        #pragma unroll
        for (int ks = 0; ks < 2; ks++) {
            const uint32_t kb = ks * 32;
            uint32_t a[2][4], b[4][2];
            LDM_X4(a[0][0], a[0][1], a[0][2], a[0][3], uA[cur] + kb);
            LDM_X4(a[1][0], a[1][1], a[1][2], a[1][3], uA[cur] + kb + 16 * GSTB);
            LDM_X4(b[0][0], b[0][1], b[1][0], b[1][1], uW[cur] + kb);
            LDM_X4(b[2][0], b[2][1], b[3][0], b[3][1], uW[cur] + kb + 16 * GSTB);
            #pragma unroll
            for (int mt = 0; mt < 2; mt++)
                #pragma unroll
                for (int nt = 0; nt < 4; nt++)
                    mma_f16(c[mt][nt], a[mt], b[nt]);
        }

        if (pf) {
            __half* Ad = As + (1 - cur) * GASZ;
            __half* Wd = Ws + (1 - cur) * GWSZ;
            *(uint4*)&Ad[ar * GST + ac]     = pah[0];
            *(uint4*)&Ad[ar * GST + ac + 8] = pah[1];
            *(uint4*)&Wd[wr * GST + wc]     = pwh;
        }
        __syncthreads();
    }

    #pragma unroll
    for (int mt = 0; mt < 2; mt++) {
        #pragma unroll
        for (int nt = 0; nt < 4; nt++) {
            int col = n0 + wn + nt * 8 + 2 * tig;
            float bx = bias[col], by = bias[col + 1];
            int r0 = m0 + wm + mt * 16 + g;
            if constexpr (sizeof(Tout) == 4) {
                *(float2*)((float*)C + (size_t)r0 * DM + col) =
                    make_float2(c[mt][nt][0] + bx, c[mt][nt][1] + by);
                *(float2*)((float*)C + (size_t)(r0 + 8) * DM + col) =
                    make_float2(c[mt][nt][2] + bx, c[mt][nt][3] + by);
            } else {
                *(uint32_t*)((__half*)C + (size_t)r0 * DM + col) =
                    packh2(c[mt][nt][0] + bx, c[mt][nt][1] + by);
                *(uint32_t*)((__half*)C + (size_t)(r0 + 8) * DM + col) =
                    packh2(c[mt][nt][2] + bx, c[mt][nt][3] + by);
            }
        }
    }
}

__global__ __launch_bounds__(256) void gemm3_kernel(
    const __half* __restrict__ qh, const __half* __restrict__ kh, const __half* __restrict__ vh,
    const __half* __restrict__ Wh,
    const float* __restrict__ bq, const float* __restrict__ bk, const float* __restrict__ bv,
    __half* Qp, __half* Kp, __half* Vp)
{
    __shared__ __half As[2 * GASZ];
    __shared__ __half Ws[2 * GWSZ];
    const __half *A, *W; const float* bias; __half* C;
    if (blockIdx.z == 0)      { A = qh; W = Wh;               bias = bq; C = Qp; }
    else if (blockIdx.z == 1) { A = kh; W = Wh + DM * DM;     bias = bk; C = Kp; }
    else                      { A = vh; W = Wh + 2 * DM * DM; bias = bv; C = Vp; }
    gemm_body<__half>(A, W, bias, C, As, Ws);
}

__global__ __launch_bounds__(256) void gemmo_kernel(
    const __half* __restrict__ Ctx, const __half* __restrict__ Woh,
    const float* __restrict__ bo, float* __restrict__ out)
{
    __shared__ __half As[2 * GASZ];
    __shared__ __half Ws[2 * GWSZ];
    gemm_body<float>(Ctx, Woh, bo, out, As, Ws);
}

// ---------------------------------------------------------------------------
// Flash attention v6: R13 shape (256 threads, 8 warps x 16 rows) +
// persistent Q register fragments + cp.async double-buffered K/V.
// ---------------------------------------------------------------------------
#define HRB  144
#define QB   0
#define KB0  (128 * HRB)
#define KB1  (KB0 + 64 * HRB)
#define VB0  (KB1 + 64 * HRB)
#define VB1  (VB0 + 64 * HRB)
#define FTOT (VB1 + 64 * HRB)       // 55296 B

__global__ __launch_bounds__(256, 2) void flash_h(
    const __half* __restrict__ Qp, const __half* __restrict__ Kp,
    const __half* __restrict__ Vp, __half* __restrict__ Ctx)
{
    extern __shared__ char smc[];
    const uint32_t uB = smem_u32(smc);

    const int t = threadIdx.x;
    const int w = t >> 5, lane = t & 31;
    const int g = lane >> 2, tig = lane & 3;
    const int s0 = blockIdx.x * 128;
    const int bh = blockIdx.y, b = bh >> 3, h = bh & 7;
    const int wm = w * 16;

    const __half* Qb = Qp + ((size_t)b * S_LEN + s0) * DM + h * DKH;
    const __half* Kb = Kp + (size_t)b * S_LEN * DM + h * DKH;
    const __half* Vb = Vp + (size_t)b * S_LEN * DM + h * DKH;

    // K/V staging via cp.async: thread t -> row t>>2, 16 halves at (t&3)*16
    const int sr = t >> 2, sc0 = (t & 3) * 16;
    const __half* kSrc = Kb + (size_t)sr * DM + sc0;
    const __half* vSrc = Vb + (size_t)sr * DM + sc0;
    const uint32_t kDst[2] = { uB + KB0 + sr * HRB + sc0 * 2,
                               uB + KB1 + sr * HRB + sc0 * 2 };
    const uint32_t vDst[2] = { uB + VB0 + sr * HRB + sc0 * 2,
                               uB + VB1 + sr * HRB + sc0 * 2 };

    // Issue tile 0 K/V copies first (overlap with Q staging)
    CP_ASYNC16(kDst[0],      kSrc);
    CP_ASYNC16(kDst[0] + 16, kSrc + 8);
    CP_ASYNC16(vDst[0],      vSrc);
    CP_ASYNC16(vDst[0] + 16, vSrc + 8);
    CP_COMMIT();

    // Stage Q (128 rows x 64 halves): 32 halves/thread
    {
        int r = t >> 1, c0 = (t & 1) * 32;
        const __half* src = Qb + (size_t)r * DM + c0;
        #pragma unroll
        for (int i = 0; i < 4; i++)
            *(uint4*)(smc + QB + r * HRB + (c0 + i * 8) * 2) = *(const uint4*)(src + i * 8);
    }
    __syncthreads();

    // Persistent Q fragments (tile-invariant): 16 regs
    const uint32_t aQ = uB + QB + wm * HRB + A_OFF(HRB);
    uint32_t qf[4][4];
    #pragma unroll
    for (int ks = 0; ks < 4; ks++)
        LDM_X4(qf[ks][0], qf[ks][1], qf[ks][2], qf[ks][3], aQ + ks * 32);

    const uint32_t aKb[2] = { uB + KB0 + B_OFF(HRB), uB + KB1 + B_OFF(HRB) };
    const uint32_t voff = (uint32_t)((lane & 15) * HRB + (lane >> 4) * 16);
    const uint32_t aVb[2] = { uB + VB0 + voff, uB + VB1 + voff };

    float oacc[8][4] = {};
    float lsum0 = 0.f, lsum1 = 0.f;
    const float CEX = 0.18033688011112042f;   // log2(e) / 8

    for (int jt = 0; jt < S_LEN / 64; jt++) {
        const int cur = jt & 1;

        CP_WAIT0();
        __syncthreads();   // tile jt visible to all; prior reads of buf[1-cur] done

        // Issue tile jt+1 copies into the other buffer
        if (jt < S_LEN / 64 - 1) {
            const __half* kp = kSrc + (size_t)(jt + 1) * 64 * DM;
            const __half* vp = vSrc + (size_t)(jt + 1) * 64 * DM;
            CP_ASYNC16(kDst[1 - cur],      kp);
            CP_ASYNC16(kDst[1 - cur] + 16, kp + 8);
            CP_ASYNC16(vDst[1 - cur],      vp);
            CP_ASYNC16(vDst[1 - cur] + 16, vp + 8);
            CP_COMMIT();
        }

        // ---- S = Q K^T  (Q from persistent registers) ----
        float scr[8][4] = {};
        {
            const uint32_t ak = aKb[cur];
            #pragma unroll
            for (int ks = 0; ks < 4; ks++) {
                const uint32_t kb = ks * 32;
                #pragma unroll
                for (int nn = 0; nn < 4; nn++) {
                    uint32_t bb[4];
                    LDM_X4(bb[0], bb[1], bb[2], bb[3], ak + kb + nn * 16 * HRB);
                    mma_f16(scr[2 * nn],     qf[ks], bb);
                    mma_f16(scr[2 * nn + 1], qf[ks], bb + 2);
                }
            }
        }

        // ---- softmax: p = exp2(s*log2e/8) packed fp16 ----
        uint32_t ap[4][4];
        #pragma unroll
        for (int nt = 0; nt < 8; nt++) {
            uint32_t p01 = ex2h2(packh2(scr[nt][0] * CEX, scr[nt][1] * CEX));
            uint32_t p23 = ex2h2(packh2(scr[nt][2] * CEX, scr[nt][3] * CEX));
            ap[nt >> 1][(nt & 1) * 2 + 0] = p01;
            ap[nt >> 1][(nt & 1) * 2 + 1] = p23;
            float2 f01 = __half22float2(*(__half2*)&p01);
            float2 f23 = __half22float2(*(__half2*)&p23);
            lsum0 += f01.x + f01.y;
            lsum1 += f23.x + f23.y;
        }

        // ---- O += P V ----
        {
            const uint32_t av = aVb[cur];
            #pragma unroll
            for (int kt = 0; kt < 4; kt++) {
                #pragma unroll
                for (int dd = 0; dd < 4; dd++) {
                    uint32_t bb[4];
                    LDM_X4T(bb[0], bb[1], bb[2], bb[3], av + kt * 16 * HRB + dd * 32);
                    mma_f16(oacc[2 * dd],     ap[kt], bb);
                    mma_f16(oacc[2 * dd + 1], ap[kt], bb + 2);
                }
            }
        }
    }

    // Row-sum reduction across tig lanes
    lsum0 += __shfl_xor_sync(0xffffffffu, lsum0, 1);
    lsum0 += __shfl_xor_sync(0xffffffffu, lsum0, 2);
    lsum1 += __shfl_xor_sync(0xffffffffu, lsum1, 1);
    lsum1 += __shfl_xor_sync(0xffffffffu, lsum1, 2);
    const float inv0 = 1.f / lsum0, inv1 = 1.f / lsum1;

    __half* d0 = Ctx + ((size_t)b * S_LEN + s0 + wm + g) * DM + h * DKH;
    __half* d1 = d0 + 8 * DM;
    #pragma unroll
    for (int nt = 0; nt < 8; nt++) {
        int col = nt * 8 + 2 * tig;
        *(uint32_t*)(d0 + col) = packh2(oacc[nt][0] * inv0, oacc[nt][1] * inv0);
        *(uint32_t*)(d1 + col) = packh2(oacc[nt][2] * inv1, oacc[nt][3] * inv1);
    }
}

// ---------------------------------------------------------------------------
extern "C" void kernel_launch(void* const* d_in, const int* in_sizes, int n_in,
                              void* d_out, int out_size)
{
    const float* q  = (const float*)d_in[0];
    const float* k  = (const float*)d_in[1];
    const float* v  = (const float*)d_in[2];
    const float* Wq = (const float*)d_in[3];
    const float* bq = (const float*)d_in[4];
    const float* Wk = (const float*)d_in[5];
    const float* bk = (const float*)d_in[6];
    const float* Wv = (const float*)d_in[7];
    const float* bv = (const float*)d_in[8];
    const float* Wo = (const float*)d_in[9];
    const float* bo = (const float*)d_in[10];
    float* out = (float*)d_out;

    const int BS = in_sizes[0] / DM;   // 8192
    const int B  = BS / S_LEN;         // 2

    float* scratch = nullptr;
    cudaGetSymbolAddress((void**)&scratch, g_scratch);
    __half* hb  = (__half*)scratch;
    __half* Qp  = hb;
    __half* Kp  = hb + 1UL * BSDM;
    __half* Vp  = hb + 2UL * BSDM;
    __half* Ctx = hb + 3UL * BSDM;
    __half* qh  = hb + 4UL * BSDM;
    __half* kh  = hb + 5UL * BSDM;
    __half* vh  = hb + 6UL * BSDM;
    __half* Wh  = hb + 7UL * BSDM;

    cvt_qkv<<<dim3((unsigned)(BSDM / (256 * 8)), 3), 256>>>(q, k, v, qh, kh, vh);
    cvt_w  <<<dim3(DM * DM / (256 * 8), 4), 256>>>(Wq, Wk, Wv, Wo, Wh);

    gemm3_kernel<<<dim3(DM / 64, BS / 128, 3), 256>>>(
        qh, kh, vh, Wh, bq, bk, bv, Qp, Kp, Vp);

    cudaFuncSetAttribute(flash_h, cudaFuncAttributeMaxDynamicSharedMemorySize, FTOT);
    flash_h<<<dim3(S_LEN / 128, NHEADS * B), 256, FTOT>>>(Qp, Kp, Vp, Ctx);

    gemmo_kernel<<<dim3(DM / 64, BS / 128), 256>>>(Ctx, Wh + 3UL * DM * DM, bo, out);
}

// round 17
// speedup vs baseline: 1.5773x; 1.5773x over previous
#include <cuda_runtime.h>
#include <cuda_fp16.h>
#include <math.h>
#include <stdint.h>

#define S_LEN  4096
#define DM     512
#define NHEADS 8
#define DKH    64
#define BSDM   (8192UL * 512UL)

__device__ float g_scratch[4UL * 8192 * 512];   // 64 MB = 32M halves

// ---------------------------------------------------------------------------
// mma / ldmatrix helpers
// ---------------------------------------------------------------------------
__device__ __forceinline__ void mma_f16(float* c, const uint32_t* a, const uint32_t* b) {
    asm volatile("mma.sync.aligned.m16n8k16.row.col.f32.f16.f16.f32 "
        "{%0,%1,%2,%3}, {%4,%5,%6,%7}, {%8,%9}, {%0,%1,%2,%3};"
        : "+f"(c[0]), "+f"(c[1]), "+f"(c[2]), "+f"(c[3])
        : "r"(a[0]), "r"(a[1]), "r"(a[2]), "r"(a[3]), "r"(b[0]), "r"(b[1]));
}
#define LDM_X4(r0, r1, r2, r3, addr) \
    asm volatile("ldmatrix.sync.aligned.m8n8.x4.shared.b16 {%0,%1,%2,%3}, [%4];" \
        : "=r"(r0), "=r"(r1), "=r"(r2), "=r"(r3) : "r"(addr))
#define LDM_X4T(r0, r1, r2, r3, addr) \
    asm volatile("ldmatrix.sync.aligned.m8n8.x4.trans.shared.b16 {%0,%1,%2,%3}, [%4];" \
        : "=r"(r0), "=r"(r1), "=r"(r2), "=r"(r3) : "r"(addr))

__device__ __forceinline__ uint32_t smem_u32(const void* p) {
    uint32_t a;
    asm("{ .reg .u64 t; cvta.to.shared.u64 t, %1; cvt.u32.u64 %0, t; }" : "=r"(a) : "l"(p));
    return a;
}
__device__ __forceinline__ uint32_t packh2(float lo, float hi) {
    __half2 h = __floats2half2_rn(lo, hi);
    return *(uint32_t*)&h;
}
__device__ __forceinline__ uint2 packh4(float4 f) {
    return make_uint2(packh2(f.x, f.y), packh2(f.z, f.w));
}
__device__ __forceinline__ uint32_t ex2h2(uint32_t x) {
    uint32_t r; asm("ex2.approx.f16x2 %0, %1;" : "=r"(r) : "r"(x)); return r;
}

#define A_OFF(RB)  (((lane & 15) * (RB)) + ((lane >> 4) * 16))
#define B_OFF(RB)  (((((lane >> 4) & 1) * 8 + (lane & 7)) * (RB)) + (((lane >> 3) & 1) * 16))

// ---------------------------------------------------------------------------
// fp32 -> fp16 pre-pass (unchanged, R13)
// ---------------------------------------------------------------------------
__global__ __launch_bounds__(256) void cvt_qkv(
    const float* __restrict__ q, const float* __restrict__ k, const float* __restrict__ v,
    __half* __restrict__ qh, __half* __restrict__ kh, __half* __restrict__ vh)
{
    const float* src; __half* dst;
    if (blockIdx.y == 0)      { src = q; dst = qh; }
    else if (blockIdx.y == 1) { src = k; dst = kh; }
    else                      { src = v; dst = vh; }
    size_t i = ((size_t)blockIdx.x * 256 + threadIdx.x) * 8;
    float4 f0 = *(const float4*)(src + i);
    float4 f1 = *(const float4*)(src + i + 4);
    *(uint4*)(dst + i) = make_uint4(packh2(f0.x, f0.y), packh2(f0.z, f0.w),
                                    packh2(f1.x, f1.y), packh2(f1.z, f1.w));
}

__global__ __launch_bounds__(256) void cvt_w(
    const float* __restrict__ Wq, const float* __restrict__ Wk,
    const float* __restrict__ Wv, const float* __restrict__ Wo,
    __half* __restrict__ Wh)
{
    const float* src;
    if (blockIdx.y == 0)      src = Wq;
    else if (blockIdx.y == 1) src = Wk;
    else if (blockIdx.y == 2) src = Wv;
    else                      src = Wo;
    __half* dst = Wh + (size_t)blockIdx.y * DM * DM;
    size_t i = ((size_t)blockIdx.x * 256 + threadIdx.x) * 8;
    float4 f0 = *(const float4*)(src + i);
    float4 f1 = *(const float4*)(src + i + 4);
    *(uint4*)(dst + i) = make_uint4(packh2(f0.x, f0.y), packh2(f0.z, f0.w),
                                    packh2(f1.x, f1.y), packh2(f1.z, f1.w));
}

// ---------------------------------------------------------------------------
// GEMM body (all-fp16 operands, fp32 accum), double-buffered. Unchanged (R13).
// ---------------------------------------------------------------------------
#define GST  40
#define GSTB 80
#define GASZ (128 * GST)
#define GWSZ (64 * GST)

template<typename Tout>
__device__ __forceinline__ void gemm_body(
    const __half* __restrict__ A, const __half* __restrict__ W,
    const float* __restrict__ bias, Tout* __restrict__ C,
    __half* As, __half* Ws)
{
    const int t = threadIdx.x;
    const int w = t >> 5, lane = t & 31;
    const int g = lane >> 2, tig = lane & 3;
    const int m0 = blockIdx.y * 128, n0 = blockIdx.x * 64;
    const int wm = (w >> 1) * 32, wn = (w & 1) * 32;
    const int ar = t >> 1, ac = (t & 1) * 16;
    const int wr = t >> 2, wc = (t & 3) * 8;

    uint32_t uA[2], uW[2];
    uA[0] = smem_u32(As) + wm * GSTB + A_OFF(GSTB);
    uA[1] = uA[0] + GASZ * 2;
    uW[0] = smem_u32(Ws) + wn * GSTB + B_OFF(GSTB);
    uW[1] = uW[0] + GWSZ * 2;

    {
        const __half* sa = A + (size_t)(m0 + ar) * DM + ac;
        *(uint4*)&As[ar * GST + ac]     = *(const uint4*)sa;
        *(uint4*)&As[ar * GST + ac + 8] = *(const uint4*)(sa + 8);
        *(uint4*)&Ws[wr * GST + wc]     = *(const uint4*)(W + (size_t)(n0 + wr) * DM + wc);
    }
    __syncthreads();

    float c[2][4][4] = {};

    for (int kt = 0; kt < DM / 32; kt++) {
        const int cur = kt & 1;
        const bool pf = (kt < DM / 32 - 1);

        uint4 pah[2], pwh;
        if (pf) {
            const int k0 = (kt + 1) * 32;
            const __half* sa = A + (size_t)(m0 + ar) * DM + k0 + ac;
            pah[0] = *(const uint4*)sa; pah[1] = *(const uint4*)(sa + 8);
            pwh = *(const uint4*)(W + (size_t)(n0 + wr) * DM + k0 + wc);
        }

        #pragma unroll
        for (int ks = 0; ks < 2; ks++) {
            const uint32_t kb = ks * 32;
            uint32_t a[2][4], b[4][2];
            LDM_X4(a[0][0], a[0][1], a[0][2], a[0][3], uA[cur] + kb);
            LDM_X4(a[1][0], a[1][1], a[1][2], a[1][3], uA[cur] + kb + 16 * GSTB);
            LDM_X4(b[0][0], b[0][1], b[1][0], b[1][1], uW[cur] + kb);
            LDM_X4(b[2][0], b[2][1], b[3][0], b[3][1], uW[cur] + kb + 16 * GSTB);
            #pragma unroll
            for (int mt = 0; mt < 2; mt++)
                #pragma unroll
                for (int nt = 0; nt < 4; nt++)
                    mma_f16(c[mt][nt], a[mt], b[nt]);
        }

        if (pf) {
            __half* Ad = As + (1 - cur) * GASZ;
            __half* Wd = Ws + (1 - cur) * GWSZ;
            *(uint4*)&Ad[ar * GST + ac]     = pah[0];
            *(uint4*)&Ad[ar * GST + ac + 8] = pah[1];
            *(uint4*)&Wd[wr * GST + wc]     = pwh;
        }
        __syncthreads();
    }

    #pragma unroll
    for (int mt = 0; mt < 2; mt++) {
        #pragma unroll
        for (int nt = 0; nt < 4; nt++) {
            int col = n0 + wn + nt * 8 + 2 * tig;
            float bx = bias[col], by = bias[col + 1];
            int r0 = m0 + wm + mt * 16 + g;
            if constexpr (sizeof(Tout) == 4) {
                *(float2*)((float*)C + (size_t)r0 * DM + col) =
                    make_float2(c[mt][nt][0] + bx, c[mt][nt][1] + by);
                *(float2*)((float*)C + (size_t)(r0 + 8) * DM + col) =
                    make_float2(c[mt][nt][2] + bx, c[mt][nt][3] + by);
            } else {
                *(uint32_t*)((__half*)C + (size_t)r0 * DM + col) =
                    packh2(c[mt][nt][0] + bx, c[mt][nt][1] + by);
                *(uint32_t*)((__half*)C + (size_t)(r0 + 8) * DM + col) =
                    packh2(c[mt][nt][2] + bx, c[mt][nt][3] + by);
            }
        }
    }
}

__global__ __launch_bounds__(256) void gemm3_kernel(
    const __half* __restrict__ qh, const __half* __restrict__ kh, const __half* __restrict__ vh,
    const __half* __restrict__ Wh,
    const float* __restrict__ bq, const float* __restrict__ bk, const float* __restrict__ bv,
    __half* Qp, __half* Kp, __half* Vp)
{
    __shared__ __half As[2 * GASZ];
    __shared__ __half Ws[2 * GWSZ];
    const __half *A, *W; const float* bias; __half* C;
    if (blockIdx.z == 0)      { A = qh; W = Wh;               bias = bq; C = Qp; }
    else if (blockIdx.z == 1) { A = kh; W = Wh + DM * DM;     bias = bk; C = Kp; }
    else                      { A = vh; W = Wh + 2 * DM * DM; bias = bv; C = Vp; }
    gemm_body<__half>(A, W, bias, C, As, Ws);
}

__global__ __launch_bounds__(256) void gemmo_kernel(
    const __half* __restrict__ Ctx, const __half* __restrict__ Woh,
    const float* __restrict__ bo, float* __restrict__ out)
{
    __shared__ __half As[2 * GASZ];
    __shared__ __half Ws[2 * GWSZ];
    gemm_body<float>(Ctx, Woh, bo, out, As, Ws);
}

// ---------------------------------------------------------------------------
// Flash attention v7: R13 staging (LDG prefetch + STS, L1-cached) +
// persistent Q fragments + kt-fused QK/exp/PV pipeline.
// ---------------------------------------------------------------------------
#define HRB  144
#define QB   0
#define KB0  (128 * HRB)
#define KB1  (KB0 + 64 * HRB)
#define VB0  (KB1 + 64 * HRB)
#define VB1  (VB0 + 64 * HRB)
#define FTOT (VB1 + 64 * HRB)       // 55296 B

__global__ __launch_bounds__(256, 2) void flash_h(
    const __half* __restrict__ Qp, const __half* __restrict__ Kp,
    const __half* __restrict__ Vp, __half* __restrict__ Ctx)
{
    extern __shared__ char smc[];
    const uint32_t uB = smem_u32(smc);

    const int t = threadIdx.x;
    const int w = t >> 5, lane = t & 31;
    const int g = lane >> 2, tig = lane & 3;
    const int s0 = blockIdx.x * 128;
    const int bh = blockIdx.y, b = bh >> 3, h = bh & 7;
    const int wm = w * 16;

    const __half* Qb = Qp + ((size_t)b * S_LEN + s0) * DM + h * DKH;
    const __half* Kb = Kp + (size_t)b * S_LEN * DM + h * DKH;
    const __half* Vb = Vp + (size_t)b * S_LEN * DM + h * DKH;

    // Stage Q (128 rows x 64 halves): 32 halves/thread
    {
        int r = t >> 1, c0 = (t & 1) * 32;
        const __half* src = Qb + (size_t)r * DM + c0;
        #pragma unroll
        for (int i = 0; i < 4; i++)
            *(uint4*)(smc + QB + r * HRB + (c0 + i * 8) * 2) = *(const uint4*)(src + i * 8);
    }

    // K/V staging (R13 scheme): thread t -> row sr, 16 halves at sc0
    const int sr = t >> 2, sc0 = (t & 3) * 16;

    const uint32_t aQ = uB + QB + wm * HRB + A_OFF(HRB);
    const uint32_t aKb[2] = { uB + KB0 + B_OFF(HRB), uB + KB1 + B_OFF(HRB) };
    const uint32_t voff = (uint32_t)((lane & 15) * HRB + (lane >> 4) * 16);
    const uint32_t aVb[2] = { uB + VB0 + voff, uB + VB1 + voff };

    // Stage tile 0 into buffer 0 (plain LDG/STS, stays in L1)
    {
        const __half* kp = Kb + (size_t)sr * DM + sc0;
        const __half* vp = Vb + (size_t)sr * DM + sc0;
        *(uint4*)(smc + KB0 + sr * HRB + sc0 * 2)      = *(const uint4*)kp;
        *(uint4*)(smc + KB0 + sr * HRB + sc0 * 2 + 16) = *(const uint4*)(kp + 8);
        *(uint4*)(smc + VB0 + sr * HRB + sc0 * 2)      = *(const uint4*)vp;
        *(uint4*)(smc + VB0 + sr * HRB + sc0 * 2 + 16) = *(const uint4*)(vp + 8);
    }
    __syncthreads();

    // Persistent Q fragments (tile-invariant, 16 regs)
    uint32_t qf[4][4];
    #pragma unroll
    for (int ks = 0; ks < 4; ks++)
        LDM_X4(qf[ks][0], qf[ks][1], qf[ks][2], qf[ks][3], aQ + ks * 32);

    float oacc[8][4] = {};
    float lsum0 = 0.f, lsum1 = 0.f;
    const float CEX = 0.18033688011112042f;   // log2(e) / 8

    for (int jt = 0; jt < S_LEN / 64; jt++) {
        const int cur = jt & 1;
        const bool pf = (jt < S_LEN / 64 - 1);

        // Prefetch next K/V tile into registers (R13 scheme)
        uint4 pk[2], pv[2];
        if (pf) {
            const __half* kp = Kb + (size_t)((jt + 1) * 64 + sr) * DM + sc0;
            const __half* vp = Vb + (size_t)((jt + 1) * 64 + sr) * DM + sc0;
            pk[0] = *(const uint4*)kp; pk[1] = *(const uint4*)(kp + 8);
            pv[0] = *(const uint4*)vp; pv[1] = *(const uint4*)(vp + 8);
        }

        // kt-fused pipeline: QK(kt) -> exp(kt) -> PV(kt), kt = 16-key chunk
        const uint32_t ak = aKb[cur];
        const uint32_t av = aVb[cur];
        #pragma unroll
        for (int kt = 0; kt < 4; kt++) {
            // S chunk: 16 rows x 16 cols (2 n-blocks), accumulate over 4 ks
            float scr2[2][4] = {};
            #pragma unroll
            for (int ks = 0; ks < 4; ks++) {
                uint32_t bb[4];
                LDM_X4(bb[0], bb[1], bb[2], bb[3], ak + ks * 32 + kt * 16 * HRB);
                mma_f16(scr2[0], qf[ks], bb);
                mma_f16(scr2[1], qf[ks], bb + 2);
            }

            // exp chunk -> fp16 A-fragment ap
            uint32_t ap[4];
            #pragma unroll
            for (int half2i = 0; half2i < 2; half2i++) {
                uint32_t p01 = ex2h2(packh2(scr2[half2i][0] * CEX, scr2[half2i][1] * CEX));
                uint32_t p23 = ex2h2(packh2(scr2[half2i][2] * CEX, scr2[half2i][3] * CEX));
                ap[half2i * 2 + 0] = p01;
                ap[half2i * 2 + 1] = p23;
                float2 f01 = __half22float2(*(__half2*)&p01);
                float2 f23 = __half22float2(*(__half2*)&p23);
                lsum0 += f01.x + f01.y;
                lsum1 += f23.x + f23.y;
            }

            // PV chunk: O += P[:, kt*16:kt*16+16] * V[kt*16:kt*16+16, :]
            #pragma unroll
            for (int dd = 0; dd < 4; dd++) {
                uint32_t bb[4];
                LDM_X4T(bb[0], bb[1], bb[2], bb[3], av + kt * 16 * HRB + dd * 32);
                mma_f16(oacc[2 * dd],     ap, bb);
                mma_f16(oacc[2 * dd + 1], ap, bb + 2);
            }
        }

        // Store K/V prefetch into the other buffer
        if (pf) {
            char* dk = smc + (cur ? KB0 : KB1) + sr * HRB + sc0 * 2;
            char* dv = smc + (cur ? VB0 : VB1) + sr * HRB + sc0 * 2;
            *(uint4*)dk = pk[0]; *(uint4*)(dk + 16) = pk[1];
            *(uint4*)dv = pv[0]; *(uint4*)(dv + 16) = pv[1];
        }
        __syncthreads();
    }

    // Row-sum reduction across tig lanes
    lsum0 += __shfl_xor_sync(0xffffffffu, lsum0, 1);
    lsum0 += __shfl_xor_sync(0xffffffffu, lsum0, 2);
    lsum1 += __shfl_xor_sync(0xffffffffu, lsum1, 1);
    lsum1 += __shfl_xor_sync(0xffffffffu, lsum1, 2);
    const float inv0 = 1.f / lsum0, inv1 = 1.f / lsum1;

    __half* d0 = Ctx + ((size_t)b * S_LEN + s0 + wm + g) * DM + h * DKH;
    __half* d1 = d0 + 8 * DM;
    #pragma unroll
    for (int nt = 0; nt < 8; nt++) {
        int col = nt * 8 + 2 * tig;
        *(uint32_t*)(d0 + col) = packh2(oacc[nt][0] * inv0, oacc[nt][1] * inv0);
        *(uint32_t*)(d1 + col) = packh2(oacc[nt][2] * inv1, oacc[nt][3] * inv1);
    }
}

// ---------------------------------------------------------------------------
extern "C" void kernel_launch(void* const* d_in, const int* in_sizes, int n_in,
                              void* d_out, int out_size)
{
    const float* q  = (const float*)d_in[0];
    const float* k  = (const float*)d_in[1];
    const float* v  = (const float*)d_in[2];
    const float* Wq = (const float*)d_in[3];
    const float* bq = (const float*)d_in[4];
    const float* Wk = (const float*)d_in[5];
    const float* bk = (const float*)d_in[6];
    const float* Wv = (const float*)d_in[7];
    const float* bv = (const float*)d_in[8];
    const float* Wo = (const float*)d_in[9];
    const float* bo = (const float*)d_in[10];
    float* out = (float*)d_out;

    const int BS = in_sizes[0] / DM;   // 8192
    const int B  = BS / S_LEN;         // 2

    float* scratch = nullptr;
    cudaGetSymbolAddress((void**)&scratch, g_scratch);
    __half* hb  = (__half*)scratch;
    __half* Qp  = hb;
    __half* Kp  = hb + 1UL * BSDM;
    __half* Vp  = hb + 2UL * BSDM;
    __half* Ctx = hb + 3UL * BSDM;
    __half* qh  = hb + 4UL * BSDM;
    __half* kh  = hb + 5UL * BSDM;
    __half* vh  = hb + 6UL * BSDM;
    __half* Wh  = hb + 7UL * BSDM;

    cvt_qkv<<<dim3((unsigned)(BSDM / (256 * 8)), 3), 256>>>(q, k, v, qh, kh, vh);
    cvt_w  <<<dim3(DM * DM / (256 * 8), 4), 256>>>(Wq, Wk, Wv, Wo, Wh);

    gemm3_kernel<<<dim3(DM / 64, BS / 128, 3), 256>>>(
        qh, kh, vh, Wh, bq, bk, bv, Qp, Kp, Vp);

    cudaFuncSetAttribute(flash_h, cudaFuncAttributeMaxDynamicSharedMemorySize, FTOT);
    flash_h<<<dim3(S_LEN / 128, NHEADS * B), 256, FTOT>>>(Qp, Kp, Vp, Ctx);

    gemmo_kernel<<<dim3(DM / 64, BS / 128), 256>>>(Ctx, Wh + 3UL * DM * DM, bo, out);
}